// round 16
// baseline (speedup 1.0000x reference)
#include <cuda_runtime.h>
#include <cuda_bf16.h>
#include <math.h>
#include <stdint.h>

#define BB 2
#define SS 2048
#define HH 2048
#define NH 16
#define HD 128
#define H3 6144

// ---------------- scratch (static device globals; no allocation) ----------------
__device__ __nv_bfloat16 g_wqkv_b[(size_t)H3 * HH];
__device__ __nv_bfloat16 g_wo_b[(size_t)HH * HH];
__device__ __nv_bfloat16 g_xhi[(size_t)BB * SS * HH];
__device__ __nv_bfloat16 g_xlo[(size_t)BB * SS * HH];
__device__ __nv_bfloat16 g_yhi[(size_t)BB * SS * HH];
__device__ __nv_bfloat16 g_ylo[(size_t)BB * SS * HH];
__device__ float g_qkv[(size_t)BB * SS * H3];
// head-major attention operands
__device__ __nv_bfloat16 g_qh[(size_t)BB * NH * SS * HD];
__device__ __nv_bfloat16 g_ql[(size_t)BB * NH * SS * HD];
__device__ __nv_bfloat16 g_kh[(size_t)BB * NH * SS * HD];
__device__ __nv_bfloat16 g_kl[(size_t)BB * NH * SS * HD];
__device__ __nv_bfloat16 g_vh[(size_t)BB * NH * HD * SS];  // transposed [b,h,d,s]
__device__ __nv_bfloat16 g_vl[(size_t)BB * NH * HD * SS];
__device__ double g_sum[2];
__device__ float g_scale[2];

// ---------------- PTX helpers (arch-agnostic, sm_80+) ----------------
__device__ __forceinline__ uint32_t s2u(const void* p) {
    uint32_t a;
    asm("{ .reg .u64 t; cvta.to.shared.u64 t, %1; cvt.u32.u64 %0, t; }"
        : "=r"(a) : "l"(p));
    return a;
}
__device__ __forceinline__ void ldsm4(uint32_t* r, uint32_t addr) {
    asm volatile("ldmatrix.sync.aligned.m8n8.x4.shared.b16 {%0,%1,%2,%3}, [%4];"
                 : "=r"(r[0]), "=r"(r[1]), "=r"(r[2]), "=r"(r[3]) : "r"(addr));
}
__device__ __forceinline__ void mma16816(float* d, const uint32_t* a,
                                         uint32_t b0, uint32_t b1) {
    asm volatile(
        "mma.sync.aligned.m16n8k16.row.col.f32.bf16.bf16.f32 "
        "{%0,%1,%2,%3}, {%4,%5,%6,%7}, {%8,%9}, {%0,%1,%2,%3};"
        : "+f"(d[0]), "+f"(d[1]), "+f"(d[2]), "+f"(d[3])
        : "r"(a[0]), "r"(a[1]), "r"(a[2]), "r"(a[3]), "r"(b0), "r"(b1));
}
__device__ __forceinline__ void cpa16(uint32_t dst, const void* src) {
    size_t g = __cvta_generic_to_global(src);
    asm volatile("cp.async.cg.shared.global [%0], [%1], 16;" :: "r"(dst), "l"(g));
}
__device__ __forceinline__ void cpa_commit() {
    asm volatile("cp.async.commit_group;" ::: "memory");
}

// ---------------- weight-scale reduction ----------------
__global__ void k_init() {
    if (threadIdx.x == 0) { g_sum[0] = 0.0; g_sum[1] = 0.0; }
}

__global__ void k_absmean(const float4* __restrict__ w, size_t n4, int idx) {
    __shared__ double sd[256];
    double local = 0.0;
    for (size_t i = (size_t)blockIdx.x * blockDim.x + threadIdx.x; i < n4;
         i += (size_t)gridDim.x * blockDim.x) {
        float4 v = w[i];
        local += (double)fabsf(v.x) + (double)fabsf(v.y)
               + (double)fabsf(v.z) + (double)fabsf(v.w);
    }
    sd[threadIdx.x] = local;
    __syncthreads();
    for (int s = 128; s > 0; s >>= 1) {
        if (threadIdx.x < s) sd[threadIdx.x] += sd[threadIdx.x + s];
        __syncthreads();
    }
    if (threadIdx.x == 0) atomicAdd(&g_sum[idx], sd[0]);
}

__global__ void k_finalize() {
    if (threadIdx.x == 0)
        g_scale[0] = (float)(g_sum[0] / (double)((size_t)H3 * HH));
    if (threadIdx.x == 1)
        g_scale[1] = (float)(g_sum[1] / (double)((size_t)HH * HH));
}

__global__ void k_quant_bf16(const float4* __restrict__ w,
                             __nv_bfloat162* __restrict__ wq, size_t n4, int idx) {
    float s = g_scale[idx] + 1e-5f;
    for (size_t i = (size_t)blockIdx.x * blockDim.x + threadIdx.x; i < n4;
         i += (size_t)gridDim.x * blockDim.x) {
        float4 v = w[i];
        wq[2 * i]     = __nv_bfloat162(__float2bfloat16_rn(rintf(v.x / s)),
                                       __float2bfloat16_rn(rintf(v.y / s)));
        wq[2 * i + 1] = __nv_bfloat162(__float2bfloat16_rn(rintf(v.z / s)),
                                       __float2bfloat16_rn(rintf(v.w / s)));
    }
}

__global__ void k_split(const float4* __restrict__ x,
                        __nv_bfloat162* __restrict__ hi,
                        __nv_bfloat162* __restrict__ lo, size_t n4) {
    for (size_t i = (size_t)blockIdx.x * blockDim.x + threadIdx.x; i < n4;
         i += (size_t)gridDim.x * blockDim.x) {
        float4 v = x[i];
        __nv_bfloat16 hx = __float2bfloat16_rn(v.x), hy = __float2bfloat16_rn(v.y);
        __nv_bfloat16 hz = __float2bfloat16_rn(v.z), hw = __float2bfloat16_rn(v.w);
        hi[2 * i]     = __nv_bfloat162(hx, hy);
        hi[2 * i + 1] = __nv_bfloat162(hz, hw);
        lo[2 * i]     = __nv_bfloat162(__float2bfloat16_rn(v.x - __bfloat162float(hx)),
                                       __float2bfloat16_rn(v.y - __bfloat162float(hy)));
        lo[2 * i + 1] = __nv_bfloat162(__float2bfloat16_rn(v.z - __bfloat162float(hz)),
                                       __float2bfloat16_rn(v.w - __bfloat162float(hw)));
    }
}

// ---------------- HMMA GEMM: 3-stage cp.async pipeline (unchanged from R14) ----------
#define GRS 40
#define GBUF (128 * GRS * 2)
#define G_STG (3 * GBUF)
#define G_SMEM (3 * G_STG)

__device__ __forceinline__ void gemm_issue(
    uint32_t sb, int st,
    const __nv_bfloat16* __restrict__ Ahi, const __nv_bfloat16* __restrict__ Alo,
    const __nv_bfloat16* __restrict__ Bq,
    int bm, int bn, int k0, int K, int lrow, int lc16)
{
    const uint32_t base = sb + st * G_STG;
    #pragma unroll
    for (int it = 0; it < 2; it++) {
        int row = lrow + (it << 6);
        size_t gofs = (size_t)row * K + k0 + (lc16 << 3);
        uint32_t sofs = row * (GRS * 2) + (lc16 << 4);
        cpa16(base + sofs,            Ahi + (size_t)bm * K + gofs);
        cpa16(base + GBUF + sofs,     Alo + (size_t)bm * K + gofs);
        cpa16(base + 2 * GBUF + sofs, Bq  + (size_t)bn * K + gofs);
    }
    cpa_commit();
}

__global__ void __launch_bounds__(256) k_gemm_mma(
    const __nv_bfloat16* __restrict__ Ahi, const __nv_bfloat16* __restrict__ Alo,
    const __nv_bfloat16* __restrict__ Bq, float* __restrict__ C,
    int M, int N, int K, int sidx)
{
    extern __shared__ char smem[];
    const uint32_t sb = s2u(smem);
    const int tid = threadIdx.x;
    const int lane = tid & 31, wid = tid >> 5;
    const int wm = wid & 1, wn = wid >> 1;
    const int bm = blockIdx.y << 7, bn = blockIdx.x << 7;

    const int lrow = tid >> 2;
    const int lc16 = tid & 3;

    float acc[4][4][4];
    #pragma unroll
    for (int i = 0; i < 4; i++)
        #pragma unroll
        for (int j = 0; j < 4; j++)
            #pragma unroll
            for (int q = 0; q < 4; q++) acc[i][j][q] = 0.f;

    const int fr = lane & 15;
    const int fk = (lane >> 4) << 3;

    gemm_issue(sb, 0, Ahi, Alo, Bq, bm, bn, 0, K, lrow, lc16);
    gemm_issue(sb, 1, Ahi, Alo, Bq, bm, bn, 32, K, lrow, lc16);

    const int NC = K >> 5;
    int st = 0;
    for (int c = 0; c < NC; c++) {
        if (c + 1 < NC)
            asm volatile("cp.async.wait_group 1;" ::: "memory");
        else
            asm volatile("cp.async.wait_group 0;" ::: "memory");
        __syncthreads();

        if (c + 2 < NC) {
            int st2 = st + 2; if (st2 >= 3) st2 -= 3;
            gemm_issue(sb, st2, Ahi, Alo, Bq, bm, bn, (c + 2) << 5, K, lrow, lc16);
        }

        const uint32_t stg = sb + st * G_STG;
        #pragma unroll
        for (int kk = 0; kk < 32; kk += 16) {
            uint32_t bf[2][4];
            #pragma unroll
            for (int p = 0; p < 2; p++) {
                uint32_t addr = stg + 2 * GBUF +
                    ((wn * 32 + p * 16 + fr) * GRS + kk + fk) * 2;
                ldsm4(bf[p], addr);
            }
            #pragma unroll
            for (int mi = 0; mi < 4; mi++) {
                uint32_t ah[4], al[4];
                uint32_t arow = ((wm * 64 + mi * 16 + fr) * GRS + kk + fk) * 2;
                ldsm4(ah, stg + arow);
                ldsm4(al, stg + GBUF + arow);
                #pragma unroll
                for (int ni = 0; ni < 4; ni++) {
                    int p = ni >> 1, j = ni & 1;
                    mma16816(acc[mi][ni], ah, bf[p][j], bf[p][j + 2]);
                    mma16816(acc[mi][ni], al, bf[p][j], bf[p][j + 2]);
                }
            }
        }
        if (++st >= 3) st -= 3;
    }

    const float sc = g_scale[sidx];
    #pragma unroll
    for (int mi = 0; mi < 4; mi++) {
        int r0 = bm + wm * 64 + mi * 16 + (lane >> 2);
        #pragma unroll
        for (int ni = 0; ni < 4; ni++) {
            int col = bn + wn * 32 + ni * 8 + ((lane & 3) << 1);
            float2 v0 = make_float2(acc[mi][ni][0] * sc, acc[mi][ni][1] * sc);
            float2 v1 = make_float2(acc[mi][ni][2] * sc, acc[mi][ni][3] * sc);
            *(float2*)&C[(size_t)r0 * N + col] = v0;
            *(float2*)&C[(size_t)(r0 + 8) * N + col] = v1;
        }
    }
}

// ---------------- prep: RoPE + hi/lo split + head-major layout + V transpose --------
__global__ void __launch_bounds__(256) k_prep(
    const float* __restrict__ qkv, const float* __restrict__ rotary,
    __nv_bfloat16* __restrict__ Qh, __nv_bfloat16* __restrict__ Ql,
    __nv_bfloat16* __restrict__ Kh, __nv_bfloat16* __restrict__ Kl,
    __nv_bfloat16* __restrict__ Vh, __nv_bfloat16* __restrict__ Vl)
{
    __shared__ float sv[64 * 132];
    const int t = threadIdx.x;
    const int stile = blockIdx.x, h = blockIdx.y, b = blockIdx.z;
    const int s0 = stile * 64;
    const int head = b * NH + h;

    const int row = t >> 2;
    const int d0 = (t & 3) << 5;
    const int pd0 = d0 ^ 64;
    const float sgn = (d0 < 64) ? -1.f : 1.f;
    const int s = s0 + row;

    #pragma unroll
    for (int part = 0; part < 2; part++) {
        const float* src = qkv + (size_t)(b * SS + s) * H3 + part * HH + h * HD;
        float v[32], pv[32], sn[32], cs[32];
        #pragma unroll
        for (int i = 0; i < 8; i++) {
            *(float4*)&v[4 * i]  = *(const float4*)(src + d0 + 4 * i);
            *(float4*)&pv[4 * i] = *(const float4*)(src + pd0 + 4 * i);
            *(float4*)&sn[4 * i] = *(const float4*)(rotary + (size_t)s * HD + d0 + 4 * i);
            *(float4*)&cs[4 * i] = *(const float4*)(rotary + (size_t)(SS + s) * HD + d0 + 4 * i);
        }
        __nv_bfloat16* dh = (part ? Kh : Qh) + ((size_t)head * SS + s) * HD + d0;
        __nv_bfloat16* dl = (part ? Kl : Ql) + ((size_t)head * SS + s) * HD + d0;
        #pragma unroll
        for (int i = 0; i < 32; i++) {
            float o = v[i] * cs[i] + sgn * pv[i] * sn[i];
            __nv_bfloat16 oh = __float2bfloat16_rn(o);
            dh[i] = oh;
            dl[i] = __float2bfloat16_rn(o - __bfloat162float(oh));
        }
    }

    for (int i = 0; i < 8; i++) {
        int id = i * 256 + t;
        int r = id >> 5, c = id & 31;
        *(float4*)&sv[r * 132 + c * 4] =
            *(const float4*)(qkv + (size_t)(b * SS + s0 + r) * H3 + 2 * HH + h * HD + c * 4);
    }
    __syncthreads();
    {
        const int d = t >> 1;
        const int sb2 = (t & 1) << 5;
        __nv_bfloat16* dh = Vh + ((size_t)head * HD + d) * SS + s0 + sb2;
        __nv_bfloat16* dl = Vl + ((size_t)head * HD + d) * SS + s0 + sb2;
        #pragma unroll
        for (int j = 0; j < 32; j++) {
            float val = sv[(sb2 + j) * 132 + d];
            __nv_bfloat16 vh2 = __float2bfloat16_rn(val);
            dh[j] = vh2;
            dl[j] = __float2bfloat16_rn(val - __bfloat162float(vh2));
        }
    }
}

// ---------------- tensor-core causal flash attention (2 CTA/SM) ----------------
// CTA: 64 q-rows, 4 warps (16 rows each), 128 threads; K/V tiles of 32 cols,
// cp.async double-buffered. smem 110,592 B -> 2 CTAs/SM.
#define AQ_RS 136
#define AV_RS 40
#define AT_QH 0
#define AT_QL 17408
#define AT_S0 34816
#define AT_STG 37888
#define AT_KH 0
#define AT_KL 8704
#define AT_VH 17408
#define AT_VL 27648
#define AT_SMEM 110592

__device__ __forceinline__ void attn_prefetch(
    int stage, int kt, int t,
    const __nv_bfloat16* kh, const __nv_bfloat16* kl,
    const __nv_bfloat16* vh, const __nv_bfloat16* vl, uint32_t sb)
{
    const uint32_t stg = sb + AT_S0 + stage * AT_STG;
    #pragma unroll
    for (int i = 0; i < 16; i++) {
        int id = i * 128 + t;                 // 0..2047
        int sel = id >> 9;                    // 0=KH 1=KL 2=VH 3=VL (512 chunks each)
        int rem = id & 511;
        if (sel < 2) {
            int r = rem >> 4, c = rem & 15;   // 32 rows x 16 chunks
            const __nv_bfloat16* src = (sel ? kl : kh) +
                (size_t)(kt * 32 + r) * HD + c * 8;
            cpa16(stg + (sel ? AT_KL : AT_KH) + (r * AQ_RS + c * 8) * 2, src);
        } else {
            int d = rem >> 2, c = rem & 3;    // 128 d-rows x 4 chunks
            const __nv_bfloat16* src = (sel == 3 ? vl : vh) +
                (size_t)d * SS + kt * 32 + c * 8;
            cpa16(stg + (sel == 3 ? AT_VL : AT_VH) + (d * AV_RS + c * 8) * 2, src);
        }
    }
    cpa_commit();
}

__global__ void __launch_bounds__(128) k_attn_tc(
    const __nv_bfloat16* __restrict__ qh_g, const __nv_bfloat16* __restrict__ ql_g,
    const __nv_bfloat16* __restrict__ kh_g, const __nv_bfloat16* __restrict__ kl_g,
    const __nv_bfloat16* __restrict__ vh_g, const __nv_bfloat16* __restrict__ vl_g,
    __nv_bfloat16* __restrict__ yhi, __nv_bfloat16* __restrict__ ylo)
{
    extern __shared__ char smem[];
    const uint32_t sb = s2u(smem);
    const int t = threadIdx.x;
    const int lane = t & 31, w = t >> 5;                   // 4 warps
    const int qt = (int)gridDim.x - 1 - (int)blockIdx.x;   // LPT order
    const int h = blockIdx.y, b = blockIdx.z;
    const int head = b * NH + h;
    const int fr = lane & 15, fk = (lane >> 4) << 3;
    const float sscale = 0.08838834764831845f;

    const __nv_bfloat16* Qhp = qh_g + ((size_t)head * SS + qt * 64) * HD;
    const __nv_bfloat16* Qlp = ql_g + ((size_t)head * SS + qt * 64) * HD;
    const __nv_bfloat16* Khp = kh_g + (size_t)head * SS * HD;
    const __nv_bfloat16* Klp = kl_g + (size_t)head * SS * HD;
    const __nv_bfloat16* Vhp = vh_g + (size_t)head * HD * SS;
    const __nv_bfloat16* Vlp = vl_g + (size_t)head * HD * SS;

    // prologue: Q (hi+lo) + stage0
    #pragma unroll
    for (int i = 0; i < 16; i++) {
        int id = i * 128 + t;                // 0..2047: 2 bufs x 64 rows x 16 chunks
        int buf = id >> 10, rem = id & 1023;
        int r = rem >> 4, c = rem & 15;
        const __nv_bfloat16* src = (buf ? Qlp : Qhp) + (size_t)r * HD + c * 8;
        cpa16(sb + (buf ? AT_QL : AT_QH) + (r * AQ_RS + c * 8) * 2, src);
    }
    cpa_commit();
    attn_prefetch(0, 0, t, Khp, Klp, Vhp, Vlp, sb);

    float oacc[16][4];
    #pragma unroll
    for (int i = 0; i < 16; i++)
        #pragma unroll
        for (int q = 0; q < 4; q++) oacc[i][q] = 0.f;
    float m0 = -1e30f, m1 = -1e30f, l0 = 0.f, l1 = 0.f;

    const int KT = 2 * qt + 2;
    for (int kt = 0; kt < KT; kt++) {
        const int stg_i = kt & 1;
        if (kt + 1 < KT) {
            attn_prefetch((kt + 1) & 1, kt + 1, t, Khp, Klp, Vhp, Vlp, sb);
            asm volatile("cp.async.wait_group 1;" ::: "memory");
        } else {
            asm volatile("cp.async.wait_group 0;" ::: "memory");
        }
        __syncthreads();

        // warp-level full-mask skip (warp rows: qt*64 + w*16 .. +15)
        if (!(kt * 32 > qt * 64 + w * 16 + 15)) {
            const uint32_t stg = sb + AT_S0 + stg_i * AT_STG;
            float sacc[4][4];
            #pragma unroll
            for (int i = 0; i < 4; i++)
                #pragma unroll
                for (int q = 0; q < 4; q++) sacc[i][q] = 0.f;

            #pragma unroll
            for (int kk = 0; kk < 8; kk++) {
                uint32_t qh4[4], ql4[4];
                uint32_t qoff = ((w * 16 + fr) * AQ_RS + kk * 16 + fk) * 2;
                ldsm4(qh4, sb + AT_QH + qoff);
                ldsm4(ql4, sb + AT_QL + qoff);
                #pragma unroll
                for (int np = 0; np < 2; np++) {
                    uint32_t khf[4], klf[4];
                    uint32_t koff = ((np * 16 + fr) * AQ_RS + kk * 16 + fk) * 2;
                    ldsm4(khf, stg + AT_KH + koff);
                    ldsm4(klf, stg + AT_KL + koff);
                    #pragma unroll
                    for (int j = 0; j < 2; j++) {
                        int nt = 2 * np + j;
                        mma16816(sacc[nt], qh4, khf[j], khf[j + 2]);
                        mma16816(sacc[nt], ql4, khf[j], khf[j + 2]);
                        mma16816(sacc[nt], qh4, klf[j], klf[j + 2]);
                    }
                }
            }

            // scale + causal mask
            const int rbase = qt * 64 + w * 16 + (lane >> 2);
            const bool domask = (kt * 32 + 31) > (qt * 64 + w * 16);
            #pragma unroll
            for (int nt = 0; nt < 4; nt++) {
                int c0 = kt * 32 + nt * 8 + ((lane & 3) << 1);
                #pragma unroll
                for (int q = 0; q < 4; q++) sacc[nt][q] *= sscale;
                if (domask) {
                    if (c0 > rbase)         sacc[nt][0] = -1e30f;
                    if (c0 + 1 > rbase)     sacc[nt][1] = -1e30f;
                    if (c0 > rbase + 8)     sacc[nt][2] = -1e30f;
                    if (c0 + 1 > rbase + 8) sacc[nt][3] = -1e30f;
                }
            }

            // online softmax
            float mt0 = -1e30f, mt1 = -1e30f;
            #pragma unroll
            for (int nt = 0; nt < 4; nt++) {
                mt0 = fmaxf(mt0, fmaxf(sacc[nt][0], sacc[nt][1]));
                mt1 = fmaxf(mt1, fmaxf(sacc[nt][2], sacc[nt][3]));
            }
            mt0 = fmaxf(mt0, __shfl_xor_sync(0xffffffffu, mt0, 1));
            mt0 = fmaxf(mt0, __shfl_xor_sync(0xffffffffu, mt0, 2));
            mt1 = fmaxf(mt1, __shfl_xor_sync(0xffffffffu, mt1, 1));
            mt1 = fmaxf(mt1, __shfl_xor_sync(0xffffffffu, mt1, 2));
            float mn0 = fmaxf(m0, mt0), mn1 = fmaxf(m1, mt1);
            float al0 = __expf(m0 - mn0), al1 = __expf(m1 - mn1);
            m0 = mn0; m1 = mn1;
            float rs0 = 0.f, rs1 = 0.f;
            #pragma unroll
            for (int nt = 0; nt < 4; nt++) {
                sacc[nt][0] = __expf(sacc[nt][0] - mn0);
                sacc[nt][1] = __expf(sacc[nt][1] - mn0);
                sacc[nt][2] = __expf(sacc[nt][2] - mn1);
                sacc[nt][3] = __expf(sacc[nt][3] - mn1);
                rs0 += sacc[nt][0] + sacc[nt][1];
                rs1 += sacc[nt][2] + sacc[nt][3];
            }
            rs0 += __shfl_xor_sync(0xffffffffu, rs0, 1);
            rs0 += __shfl_xor_sync(0xffffffffu, rs0, 2);
            rs1 += __shfl_xor_sync(0xffffffffu, rs1, 1);
            rs1 += __shfl_xor_sync(0xffffffffu, rs1, 2);
            l0 = l0 * al0 + rs0;
            l1 = l1 * al1 + rs1;
            #pragma unroll
            for (int i = 0; i < 16; i++) {
                oacc[i][0] *= al0; oacc[i][1] *= al0;
                oacc[i][2] *= al1; oacc[i][3] *= al1;
            }

            // P -> bf16 hi/lo fragments, then PV
            #pragma unroll
            for (int kk2 = 0; kk2 < 2; kk2++) {
                uint32_t ph4[4], pl4[4];
                #pragma unroll
                for (int half = 0; half < 2; half++) {
                    int nt = 2 * kk2 + half;
                    #pragma unroll
                    for (int rr = 0; rr < 2; rr++) {
                        float f0 = sacc[nt][2 * rr], f1 = sacc[nt][2 * rr + 1];
                        __nv_bfloat16 h0 = __float2bfloat16_rn(f0);
                        __nv_bfloat16 h1 = __float2bfloat16_rn(f1);
                        __nv_bfloat162 ph2(h0, h1);
                        __nv_bfloat162 pl2(
                            __float2bfloat16_rn(f0 - __bfloat162float(h0)),
                            __float2bfloat16_rn(f1 - __bfloat162float(h1)));
                        ph4[half * 2 + rr] = *(uint32_t*)&ph2;
                        pl4[half * 2 + rr] = *(uint32_t*)&pl2;
                    }
                }
                #pragma unroll
                for (int dp = 0; dp < 8; dp++) {
                    uint32_t vhf[4], vlf[4];
                    uint32_t voff = ((dp * 16 + fr) * AV_RS + kk2 * 16 + fk) * 2;
                    ldsm4(vhf, stg + AT_VH + voff);
                    ldsm4(vlf, stg + AT_VL + voff);
                    #pragma unroll
                    for (int j = 0; j < 2; j++) {
                        int nt = 2 * dp + j;
                        mma16816(oacc[nt], ph4, vhf[j], vhf[j + 2]);
                        mma16816(oacc[nt], pl4, vhf[j], vhf[j + 2]);
                        mma16816(oacc[nt], ph4, vlf[j], vlf[j + 2]);
                    }
                }
            }
        }
        __syncthreads();
    }

    // epilogue: normalize, split hi/lo, store
    float inv0 = 1.f / l0, inv1 = 1.f / l1;
    int row0 = b * SS + qt * 64 + w * 16 + (lane >> 2);
    #pragma unroll
    for (int nt = 0; nt < 16; nt++) {
        int col = h * 128 + nt * 8 + ((lane & 3) << 1);
        #pragma unroll
        for (int rr = 0; rr < 2; rr++) {
            float f0 = oacc[nt][2 * rr] * (rr ? inv1 : inv0);
            float f1 = oacc[nt][2 * rr + 1] * (rr ? inv1 : inv0);
            __nv_bfloat16 h0 = __float2bfloat16_rn(f0);
            __nv_bfloat16 h1 = __float2bfloat16_rn(f1);
            __nv_bfloat162 vh2(h0, h1);
            __nv_bfloat162 vl2(__float2bfloat16_rn(f0 - __bfloat162float(h0)),
                               __float2bfloat16_rn(f1 - __bfloat162float(h1)));
            size_t off = (size_t)(row0 + rr * 8) * HH + col;
            *(__nv_bfloat162*)&yhi[off] = vh2;
            *(__nv_bfloat162*)&ylo[off] = vl2;
        }
    }
}

// ---------------- launch ----------------
extern "C" void kernel_launch(void* const* d_in, const int* in_sizes, int n_in,
                              void* d_out, int out_size) {
    (void)in_sizes; (void)n_in; (void)out_size;
    const float* x      = (const float*)d_in[0];
    const float* rotary = (const float*)d_in[1];
    const float* wqkv   = (const float*)d_in[2];
    const float* wo     = (const float*)d_in[3];
    float* out = (float*)d_out;

    __nv_bfloat16 *p_wqkv_b, *p_wo_b, *p_xhi, *p_xlo, *p_yhi, *p_ylo;
    __nv_bfloat16 *p_qh, *p_ql, *p_kh, *p_kl, *p_vh, *p_vl;
    float *p_qkv;
    cudaGetSymbolAddress((void**)&p_wqkv_b, g_wqkv_b);
    cudaGetSymbolAddress((void**)&p_wo_b,   g_wo_b);
    cudaGetSymbolAddress((void**)&p_xhi,    g_xhi);
    cudaGetSymbolAddress((void**)&p_xlo,    g_xlo);
    cudaGetSymbolAddress((void**)&p_yhi,    g_yhi);
    cudaGetSymbolAddress((void**)&p_ylo,    g_ylo);
    cudaGetSymbolAddress((void**)&p_qkv,    g_qkv);
    cudaGetSymbolAddress((void**)&p_qh,     g_qh);
    cudaGetSymbolAddress((void**)&p_ql,     g_ql);
    cudaGetSymbolAddress((void**)&p_kh,     g_kh);
    cudaGetSymbolAddress((void**)&p_kl,     g_kl);
    cudaGetSymbolAddress((void**)&p_vh,     g_vh);
    cudaGetSymbolAddress((void**)&p_vl,     g_vl);

    cudaFuncSetAttribute(k_gemm_mma, cudaFuncAttributeMaxDynamicSharedMemorySize,
                         G_SMEM);
    cudaFuncSetAttribute(k_attn_tc, cudaFuncAttributeMaxDynamicSharedMemorySize,
                         AT_SMEM);

    // scales
    k_init<<<1, 32>>>();
    k_absmean<<<2048, 256>>>((const float4*)wqkv, (size_t)H3 * HH / 4, 0);
    k_absmean<<<1024, 256>>>((const float4*)wo,   (size_t)HH * HH / 4, 1);
    k_finalize<<<1, 32>>>();

    // ternary quantization -> bf16
    k_quant_bf16<<<4096, 256>>>((const float4*)wqkv, (__nv_bfloat162*)p_wqkv_b,
                                (size_t)H3 * HH / 4, 0);
    k_quant_bf16<<<2048, 256>>>((const float4*)wo, (__nv_bfloat162*)p_wo_b,
                                (size_t)HH * HH / 4, 1);

    // split x
    k_split<<<2048, 256>>>((const float4*)x, (__nv_bfloat162*)p_xhi,
                           (__nv_bfloat162*)p_xlo, (size_t)BB * SS * HH / 4);

    // qkv = x @ Wq^T * scale
    {
        dim3 grid(H3 / 128, (BB * SS) / 128);
        k_gemm_mma<<<grid, 256, G_SMEM>>>(p_xhi, p_xlo, p_wqkv_b, p_qkv,
                                          BB * SS, H3, HH, 0);
    }

    // RoPE + hi/lo + head-major + V transpose
    {
        dim3 grid(SS / 64, NH, BB);
        k_prep<<<grid, 256>>>(p_qkv, rotary, p_qh, p_ql, p_kh, p_kl, p_vh, p_vl);
    }

    // tensor-core causal flash attention -> yhi/ylo  (64-row q tiles, 2 CTA/SM)
    {
        dim3 grid(SS / 64, NH, BB);
        k_attn_tc<<<grid, 128, AT_SMEM>>>(p_qh, p_ql, p_kh, p_kl, p_vh, p_vl,
                                          p_yhi, p_ylo);
    }

    // out = y @ Wq_o^T * scale
    {
        dim3 grid(HH / 128, (BB * SS) / 128);
        k_gemm_mma<<<grid, 256, G_SMEM>>>(p_yhi, p_ylo, p_wo_b, out,
                                          BB * SS, HH, HH, 1);
    }
}